// round 4
// baseline (speedup 1.0000x reference)
#include <cuda_runtime.h>

#define W 8192
#define H 2048
#define NPIX (W * H)

#define FOV_SPAN     0.5235987755982988f   // 30 deg in rad
#define FOV_ABS_DOWN 0.2617993877991494f   // 15 deg in rad
#define TWO_PI       6.283185307179586f
#define PI_F         3.141592653589793f

// Rotation by one column step, theta = 2*pi/8192.
#define ROT_C 0.999999705862867f
#define ROT_S 0.000766990318746f

// Eighth-density yaw table (8 KB) + pitch table (8 KB): L1/L2 resident.
static __device__ float2 g_cs_yaw8[W / 8];
static __device__ float  g_sin_pitch[H];

__global__ void fill_tables_kernel() {
    int t = blockIdx.x * blockDim.x + threadIdx.x;
    if (t < W / 8) {
        float yaw = (float)(8 * t) / (float)W * TWO_PI - PI_F;
        float s, c;
        sincosf(yaw, &s, &c);
        g_cs_yaw8[t] = make_float2(c, s);
    }
    if (t < H) {
        float pitch = (1.0f - (float)t / (float)H) * FOV_SPAN - FOV_ABS_DOWN;
        g_sin_pitch[t] = sinf(pitch);
    }
}

// Forced 128-bit streaming load: ptxas must not narrow to LDG.32
// (that quadruples L1 wavefronts; full-width is free in DRAM terms since
// every 32B sector holds 2 depths anyway).
__device__ __forceinline__ float ldg128_depth_cs(const float4* a) {
    float x, y, z, w;
    asm volatile("ld.global.cs.v4.f32 {%0,%1,%2,%3}, [%4];"
                 : "=f"(x), "=f"(y), "=f"(z), "=f"(w) : "l"(a));
    return w;
}

// Each thread: 8 consecutive pixels of one row.
//   warp reads 4 KB contiguous (8 front-batched LDG.128),
//   writes 3 KB contiguous (6 STG.128) -> long same-direction DRAM bursts.
__global__ void __launch_bounds__(256)
proj_to_pointcloud_kernel(const float4* __restrict__ img, float4* __restrict__ out) {
    int t = blockIdx.x * blockDim.x + threadIdx.x;
    long p = (long)t << 3;       // base pixel (multiple of 8, same row)
    int i = (int)(p >> 13);      // row
    int g = t & (W / 8 - 1);     // yaw-group index (column j = 8g)

    // Front-batch all 8 vector loads for MLP + burst locality.
    float d0 = ldg128_depth_cs(img + p);
    float d1 = ldg128_depth_cs(img + p + 1);
    float d2 = ldg128_depth_cs(img + p + 2);
    float d3 = ldg128_depth_cs(img + p + 3);
    float d4 = ldg128_depth_cs(img + p + 4);
    float d5 = ldg128_depth_cs(img + p + 5);
    float d6 = ldg128_depth_cs(img + p + 6);
    float d7 = ldg128_depth_cs(img + p + 7);

    float  sp  = g_sin_pitch[i];
    float2 cs0 = g_cs_yaw8[g];   // lane t reads entry t: fully coalesced

    // Givens chain: (c,s) -> (c*C - s*S, s*C + c*S), 7 steps.
    float c0 = cs0.x, s0 = cs0.y;
    float c1 = fmaf(c0, ROT_C, -s0 * ROT_S), s1 = fmaf(s0, ROT_C, c0 * ROT_S);
    float c2 = fmaf(c1, ROT_C, -s1 * ROT_S), s2 = fmaf(s1, ROT_C, c1 * ROT_S);
    float c3 = fmaf(c2, ROT_C, -s2 * ROT_S), s3 = fmaf(s2, ROT_C, c2 * ROT_S);
    float c4 = fmaf(c3, ROT_C, -s3 * ROT_S), s4 = fmaf(s3, ROT_C, c3 * ROT_S);
    float c5 = fmaf(c4, ROT_C, -s4 * ROT_S), s5 = fmaf(s4, ROT_C, c4 * ROT_S);
    float c6 = fmaf(c5, ROT_C, -s5 * ROT_S), s6 = fmaf(s5, ROT_C, c5 * ROT_S);
    float c7 = fmaf(c6, ROT_C, -s6 * ROT_S), s7 = fmaf(s6, ROT_C, c6 * ROT_S);

    float x0 =  d0 * c0, y0 = -d0 * s0, z0 = d0 * sp;
    float x1 =  d1 * c1, y1 = -d1 * s1, z1 = d1 * sp;
    float x2 =  d2 * c2, y2 = -d2 * s2, z2 = d2 * sp;
    float x3 =  d3 * c3, y3 = -d3 * s3, z3 = d3 * sp;
    float x4 =  d4 * c4, y4 = -d4 * s4, z4 = d4 * sp;
    float x5 =  d5 * c5, y5 = -d5 * s5, z5 = d5 * sp;
    float x6 =  d6 * c6, y6 = -d6 * s6, z6 = d6 * sp;
    float x7 =  d7 * c7, y7 = -d7 * s7, z7 = d7 * sp;

    long ob = (long)t * 6;
    __stcs(out + ob,     make_float4(x0, y0, z0, x1));
    __stcs(out + ob + 1, make_float4(y1, z1, x2, y2));
    __stcs(out + ob + 2, make_float4(z2, x3, y3, z3));
    __stcs(out + ob + 3, make_float4(x4, y4, z4, x5));
    __stcs(out + ob + 4, make_float4(y5, z5, x6, y6));
    __stcs(out + ob + 5, make_float4(z6, x7, y7, z7));
}

extern "C" void kernel_launch(void* const* d_in, const int* in_sizes, int n_in,
                              void* d_out, int out_size) {
    const float4* img = (const float4*)d_in[0];
    float4* out = (float4*)d_out;

    // Prologue: 2048 threads over 16 blocks (spread across SMs, shorter tail).
    fill_tables_kernel<<<16, 128>>>();

    int threads = 256;
    int total_threads = NPIX / 8;            // 2,097,152
    int blocks = total_threads / threads;    // 8,192
    proj_to_pointcloud_kernel<<<blocks, threads>>>(img, out);
}

// round 5
// speedup vs baseline: 1.1649x; 1.1649x over previous
#include <cuda_runtime.h>

#define W 8192
#define H 2048
#define NPIX (W * H)
#define PX_PER_BLOCK 1024
#define THREADS 256
#define NBLOCKS (NPIX / PX_PER_BLOCK)   // 16384

#define FOV_SPAN     0.5235987755982988f   // 30 deg in rad
#define FOV_ABS_DOWN 0.2617993877991494f   // 15 deg in rad
#define TWO_PI       6.283185307179586f
#define PI_F         3.141592653589793f

// Rotation by 256 column steps: delta = 256 * 2*pi/8192 = pi/16
#define ROT_C 0.9807852804032304f
#define ROT_S 0.1950903220161283f

// Full-density yaw table (64 KB) + pitch table (8 KB). L2-resident.
static __device__ float2 g_cs_yaw[W];
static __device__ float  g_sin_pitch[H];

__global__ void fill_tables_kernel() {
    int t = blockIdx.x * blockDim.x + threadIdx.x;
    if (t < W) {
        float yaw = (float)t / (float)W * TWO_PI - PI_F;
        float s, c;
        sincosf(yaw, &s, &c);
        g_cs_yaw[t] = make_float2(c, s);
    }
    if (t < H) {
        float pitch = (1.0f - (float)t / (float)H) * FOV_SPAN - FOV_ABS_DOWN;
        g_sin_pitch[t] = sinf(pitch);
    }
}

// Block: 1024 consecutive pixels of one row (1024 | 8192, never crosses rows).
// Phase 1: warp-interleaved depth loads (unit 16B lane stride -> min wavefronts),
//          compute, scalar-stage xyz into smem (stride-3 -> bank-conflict-free).
// Phase 2: unit-stride LDS.128 + STG.128 -> minimum store wavefronts,
//          every store wavefront is a full 128B line.
__global__ void __launch_bounds__(THREADS)
proj_to_pointcloud_kernel(const float* __restrict__ img, float4* __restrict__ out) {
    __shared__ float4 s_tile4[PX_PER_BLOCK * 3 / 4];     // 12 KB
    float* s_tile = (float*)s_tile4;

    int t = threadIdx.x;
    long blockBase = (long)blockIdx.x * PX_PER_BLOCK;    // first pixel of block
    int row = (int)(blockBase >> 13);                    // / 8192
    int j0  = (int)(blockBase & (W - 1));                // column of pixel 0

    float  sp = g_sin_pitch[row];
    float2 cs = g_cs_yaw[j0 + t];                        // coalesced: lane t -> entry j0+t
    float  c  = cs.x, s = cs.y;

    #pragma unroll
    for (int i = 0; i < 4; i++) {
        int p = i * THREADS + t;                         // pixel within block
        // depth = channel 3 of pixel; scalar streaming load, 16B lane stride
        float d = __ldcs(img + (((blockBase + p) << 2) + 3));

        float x =  d * c;
        float y = -d * s;
        float z =  d * sp;
        s_tile[3 * p + 0] = x;                           // stride-3: conflict-free
        s_tile[3 * p + 1] = y;
        s_tile[3 * p + 2] = z;

        // advance yaw by 256 columns for next chunk
        float cn = fmaf(c, ROT_C, -s * ROT_S);
        float sn = fmaf(s, ROT_C,  c * ROT_S);
        c = cn; s = sn;
    }

    __syncthreads();

    // 768 float4 per block; thread t handles t, t+256, t+512 (unit lane stride)
    float4* outb = out + (long)blockIdx.x * (PX_PER_BLOCK * 3 / 4);
    #pragma unroll
    for (int k = 0; k < 3; k++) {
        __stcs(outb + k * THREADS + t, s_tile4[k * THREADS + t]);
    }
}

extern "C" void kernel_launch(void* const* d_in, const int* in_sizes, int n_in,
                              void* d_out, int out_size) {
    const float* img = (const float*)d_in[0];
    float4* out = (float4*)d_out;

    fill_tables_kernel<<<(W + 255) / 256, 256>>>();
    proj_to_pointcloud_kernel<<<NBLOCKS, THREADS>>>(img, out);
}

// round 6
// speedup vs baseline: 1.2012x; 1.0312x over previous
#include <cuda_runtime.h>
#include <cstdint>

#define W 8192
#define H 2048
#define NPIX (W * H)
#define THREADS 512
#define PX_PER_BLOCK 2048
#define PX_PER_THREAD 4
#define NBLOCKS (NPIX / PX_PER_BLOCK)        // 16384
#define OUT_BYTES_PER_BLOCK (PX_PER_BLOCK * 3 * 4)  // 24576

#define FOV_SPAN     0.5235987755982988f
#define FOV_ABS_DOWN 0.2617993877991494f
#define TWO_PI       6.283185307179586f
#define PI_F         3.141592653589793f

// Rotation by 512 column steps: delta = 512 * 2*pi/8192 = pi/8
#define ROT_C 0.9238795325112867f
#define ROT_S 0.3826834323650898f

// Full-density yaw table (64 KB) + pitch table (8 KB). L2-resident.
static __device__ float2 g_cs_yaw[W];
static __device__ float  g_sin_pitch[H];

__global__ void fill_tables_kernel() {
    int t = blockIdx.x * blockDim.x + threadIdx.x;
    if (t < W) {
        float yaw = (float)t / (float)W * TWO_PI - PI_F;
        float s, c;
        sincosf(yaw, &s, &c);
        g_cs_yaw[t] = make_float2(c, s);
    }
    if (t < H) {
        float pitch = (1.0f - (float)t / (float)H) * FOV_SPAN - FOV_ABS_DOWN;
        g_sin_pitch[t] = sinf(pitch);
    }
}

__device__ __forceinline__ uint32_t smem_u32(const void* p) {
    uint32_t a;
    asm("{ .reg .u64 t; cvta.to.shared.u64 t, %1; cvt.u32.u64 %0, t; }"
        : "=r"(a) : "l"(p));
    return a;
}

// Block: 2048 consecutive pixels of one row (2048 | 8192).
// Phase 1: warp-interleaved scalar depth loads (16B lane stride = min wf),
//          compute, stage xyz in smem (stride-3 scalar STS, conflict-free).
// Phase 2: ONE cp.async.bulk (24 KB smem -> gmem) per block. The TMA engine
//          presents the write stream as large monolithic bursts instead of
//          per-warp 128B STG crumbs -> fewer DRAM read/write turnarounds.
__global__ void __launch_bounds__(THREADS)
proj_to_pointcloud_kernel(const float* __restrict__ img, float* __restrict__ out) {
    __shared__ float s_tile[PX_PER_BLOCK * 3];           // 24 KB

    int t = threadIdx.x;
    long blockBase = (long)blockIdx.x * PX_PER_BLOCK;    // first pixel of block
    int row = (int)(blockBase >> 13);
    int j0  = (int)(blockBase & (W - 1));

    float  sp = g_sin_pitch[row];
    float2 cs = g_cs_yaw[j0 + t];                        // coalesced
    float  c  = cs.x, s = cs.y;

    // Front-batch the 4 depth loads (independent, MLP=4).
    float d[PX_PER_THREAD];
    #pragma unroll
    for (int i = 0; i < PX_PER_THREAD; i++) {
        long px = blockBase + i * THREADS + t;
        d[i] = __ldcs(img + ((px << 2) + 3));
    }

    #pragma unroll
    for (int i = 0; i < PX_PER_THREAD; i++) {
        int p = i * THREADS + t;
        s_tile[3 * p + 0] =  d[i] * c;
        s_tile[3 * p + 1] = -d[i] * s;
        s_tile[3 * p + 2] =  d[i] * sp;
        // advance yaw by 512 columns (pi/8)
        float cn = fmaf(c, ROT_C, -s * ROT_S);
        float sn = fmaf(s, ROT_C,  c * ROT_S);
        c = cn; s = sn;
    }

    __syncthreads();

    // Single bulk store: 24 KB contiguous, issued by one thread.
    if (t == 0) {
        // Order generic-proxy smem writes before async-proxy read.
        asm volatile("fence.proxy.async.shared::cta;" ::: "memory");
        uint32_t src = smem_u32(s_tile);
        const float* dst = out + (long)blockIdx.x * (PX_PER_BLOCK * 3);
        asm volatile(
            "cp.async.bulk.global.shared::cta.bulk_group [%0], [%1], %2;"
            :: "l"(dst), "r"(src), "n"(OUT_BYTES_PER_BLOCK) : "memory");
        asm volatile("cp.async.bulk.commit_group;" ::: "memory");
        // Hold smem alive until the TMA read of it has completed.
        asm volatile("cp.async.bulk.wait_group.read 0;" ::: "memory");
    }
}

extern "C" void kernel_launch(void* const* d_in, const int* in_sizes, int n_in,
                              void* d_out, int out_size) {
    const float* img = (const float*)d_in[0];
    float* out = (float*)d_out;

    fill_tables_kernel<<<(W + 255) / 256, 256>>>();
    proj_to_pointcloud_kernel<<<NBLOCKS, THREADS>>>(img, out);
}

// round 7
// speedup vs baseline: 1.2278x; 1.0221x over previous
#include <cuda_runtime.h>
#include <cstdint>

#define W 8192
#define H 2048
#define NPIX (W * H)
#define THREADS 256
#define PX_PER_BLOCK 1024
#define NBLOCKS (NPIX / PX_PER_BLOCK)            // 16384
#define IMG_BYTES_PER_BLOCK (PX_PER_BLOCK * 16)  // 16384
#define OUT_BYTES_PER_BLOCK (PX_PER_BLOCK * 12)  // 12288

#define FOV_SPAN     0.5235987755982988f
#define FOV_ABS_DOWN 0.2617993877991494f
#define TWO_PI       6.283185307179586f
#define PI_F         3.141592653589793f

// Rotation by 256 column steps: delta = 256 * 2*pi/8192 = pi/16
#define ROT_C 0.9807852804032304f
#define ROT_S 0.1950903220161283f

__device__ __forceinline__ uint32_t smem_u32(const void* p) {
    uint32_t a;
    asm("{ .reg .u64 t; cvta.to.shared.u64 t, %1; cvt.u32.u64 %0, t; }"
        : "=r"(a) : "l"(p));
    return a;
}

// Single kernel, no tables, no prologue.
// Per block (1024 consecutive pixels of one row; 1024 | 8192):
//   1. thread 0 issues ONE cp.async.bulk gmem->smem (16 KB image tile)
//   2. all threads compute sincosf(yaw)/sinf(pitch) WHILE the TMA is in flight
//   3. wait mbarrier; read depths from smem; stage xyz into smem
//   4. ONE cp.async.bulk smem->gmem (12 KB)
// Both directions now hit DRAM as monolithic bursts -> minimal R/W turnaround.
__global__ void __launch_bounds__(THREADS)
proj_to_pointcloud_kernel(const float* __restrict__ img, float* __restrict__ out) {
    __shared__ alignas(128) float s_img[PX_PER_BLOCK * 4];   // 16 KB
    __shared__ alignas(128) float s_out[PX_PER_BLOCK * 3];   // 12 KB
    __shared__ alignas(8)   uint64_t s_mbar;

    int t = threadIdx.x;
    long blockBase = (long)blockIdx.x * PX_PER_BLOCK;
    int row = (int)(blockBase >> 13);
    int j0  = (int)(blockBase & (W - 1));
    uint32_t mb = smem_u32(&s_mbar);

    if (t == 0) {
        asm volatile("mbarrier.init.shared.b64 [%0], %1;" :: "r"(mb), "r"(1));
    }
    __syncthreads();

    if (t == 0) {
        asm volatile("mbarrier.arrive.expect_tx.shared.b64 _, [%0], %1;"
                     :: "r"(mb), "r"(IMG_BYTES_PER_BLOCK) : "memory");
        uint32_t dstp = smem_u32(s_img);
        const float* srcp = img + (blockBase << 2);
        asm volatile(
            "cp.async.bulk.shared::cta.global.mbarrier::complete_tx::bytes "
            "[%0], [%1], %2, [%3];"
            :: "r"(dstp), "l"(srcp), "n"(IMG_BYTES_PER_BLOCK), "r"(mb) : "memory");
    }

    // ---- trig, overlapped with the TMA load ----
    // yaw = j/W * 2pi - pi  (j/8192 exact in f32, so scaling order is exact-equal)
    float yaw = (float)(j0 + t) * (TWO_PI / (float)W) - PI_F;
    float s, c;
    sincosf(yaw, &s, &c);
    float pitch = (1.0f - (float)row / (float)H) * FOV_SPAN - FOV_ABS_DOWN;
    float sp = sinf(pitch);

    // ---- wait for image tile ----
    asm volatile(
        "{\n\t"
        ".reg .pred P;\n\t"
        "WAIT_%=:\n\t"
        "mbarrier.try_wait.parity.acquire.cta.shared::cta.b64 P, [%0], %1, 0x989680;\n\t"
        "@P bra DONE_%=;\n\t"
        "bra WAIT_%=;\n\t"
        "DONE_%=:\n\t"
        "}" :: "r"(mb), "r"(0) : "memory");

    #pragma unroll
    for (int i = 0; i < PX_PER_BLOCK / THREADS; i++) {
        int p = i * THREADS + t;
        float d = s_img[4 * p + 3];          // depth channel
        s_out[3 * p + 0] =  d * c;
        s_out[3 * p + 1] = -d * s;
        s_out[3 * p + 2] =  d * sp;
        // advance yaw by 256 columns (pi/16 Givens rotation)
        float cn = fmaf(c, ROT_C, -s * ROT_S);
        float sn = fmaf(s, ROT_C,  c * ROT_S);
        c = cn; s = sn;
    }

    __syncthreads();

    if (t == 0) {
        asm volatile("fence.proxy.async.shared::cta;" ::: "memory");
        uint32_t srcp = smem_u32(s_out);
        const float* dstp = out + blockBase * 3;
        asm volatile(
            "cp.async.bulk.global.shared::cta.bulk_group [%0], [%1], %2;"
            :: "l"(dstp), "r"(srcp), "n"(OUT_BYTES_PER_BLOCK) : "memory");
        asm volatile("cp.async.bulk.commit_group;" ::: "memory");
        // keep smem alive until the TMA has read it
        asm volatile("cp.async.bulk.wait_group.read 0;" ::: "memory");
    }
}

extern "C" void kernel_launch(void* const* d_in, const int* in_sizes, int n_in,
                              void* d_out, int out_size) {
    const float* img = (const float*)d_in[0];
    float* out = (float*)d_out;
    proj_to_pointcloud_kernel<<<NBLOCKS, THREADS>>>(img, out);
}